// round 5
// baseline (speedup 1.0000x reference)
#include <cuda_runtime.h>
#include <cuda_bf16.h>

#define NNODES 100000
#define NEDGES 600000
#define DFEAT  128

// Scratch (__device__ globals; never materialized host-side)
__device__ float g_dis[NNODES];     // deg -> rsqrt(deg)
__device__ float g_h0[NNODES];      // y = X w
__device__ float g_h1[NNODES];      // after round 1
__device__ float g_wedge[NEDGES];   // dis[row]*dis[col], cached in round 1

// K1: init deg=1 (self loop), zero h1, out = b
__global__ void k_init(float* __restrict__ out, const float* __restrict__ b) {
    int i = blockIdx.x * blockDim.x + threadIdx.x;
    if (i < NNODES) {
        g_dis[i] = 1.0f;
        g_h1[i]  = 0.0f;
        out[i]   = b[0];
    }
}

// K2: degree count, 4 edges/thread (NEDGES % 4 == 0)
__global__ void k_count_deg(const int* __restrict__ ei) {
    int t = blockIdx.x * blockDim.x + threadIdx.x;
    int e = t * 4;
    if (e < NEDGES) {
        int4 c4 = *reinterpret_cast<const int4*>(ei + NEDGES + e);
        atomicAdd(&g_dis[c4.x], 1.0f);
        atomicAdd(&g_dis[c4.y], 1.0f);
        atomicAdd(&g_dis[c4.z], 1.0f);
        atomicAdd(&g_dis[c4.w], 1.0f);
    }
}

// K3: y = X w, 4 nodes per warp (MLP=4), plus dis = rsqrt(deg)
__global__ void k_dot(const float* __restrict__ x, const float* __restrict__ w) {
    int warp_id = (blockIdx.x * blockDim.x + threadIdx.x) >> 5;
    int lane = threadIdx.x & 31;
    int base = warp_id * 4;
    if (base >= NNODES) return;   // NNODES % 4 == 0

    if (lane < 4) g_dis[base + lane] = rsqrtf(g_dis[base + lane]);

    const float4* wr = reinterpret_cast<const float4*>(w);
    float4 wv = __ldg(&wr[lane]);

    float4 xv0 = reinterpret_cast<const float4*>(x + (size_t)(base + 0) * DFEAT)[lane];
    float4 xv1 = reinterpret_cast<const float4*>(x + (size_t)(base + 1) * DFEAT)[lane];
    float4 xv2 = reinterpret_cast<const float4*>(x + (size_t)(base + 2) * DFEAT)[lane];
    float4 xv3 = reinterpret_cast<const float4*>(x + (size_t)(base + 3) * DFEAT)[lane];

    float s0 = xv0.x * wv.x + xv0.y * wv.y + xv0.z * wv.z + xv0.w * wv.w;
    float s1 = xv1.x * wv.x + xv1.y * wv.y + xv1.z * wv.z + xv1.w * wv.w;
    float s2 = xv2.x * wv.x + xv2.y * wv.y + xv2.z * wv.z + xv2.w * wv.w;
    float s3 = xv3.x * wv.x + xv3.y * wv.y + xv3.z * wv.z + xv3.w * wv.w;

    #pragma unroll
    for (int off = 16; off > 0; off >>= 1) {
        s0 += __shfl_xor_sync(0xFFFFFFFFu, s0, off);
        s1 += __shfl_xor_sync(0xFFFFFFFFu, s1, off);
        s2 += __shfl_xor_sync(0xFFFFFFFFu, s2, off);
        s3 += __shfl_xor_sync(0xFFFFFFFFu, s3, off);
    }

    if (lane == 0) {
        *reinterpret_cast<float4*>(&g_h0[base]) = make_float4(s0, s1, s2, s3);
    }
}

// K4: round 1 — self term (scalar range) + edge scatter 4/thread,
// caching wedge = dis[row]*dis[col] for round 2.
#define NODE_T NNODES
__global__ void k_round1(const int* __restrict__ ei) {
    int t = blockIdx.x * blockDim.x + threadIdx.x;
    if (t < NODE_T) {
        float d = g_dis[t];
        atomicAdd(&g_h1[t], d * d * g_h0[t]);
    } else {
        int e = (t - NODE_T) * 4;
        if (e < NEDGES) {
            int4 r4 = *reinterpret_cast<const int4*>(ei + e);
            int4 c4 = *reinterpret_cast<const int4*>(ei + NEDGES + e);
            // 12 independent gathers in flight
            float dr0 = __ldg(&g_dis[r4.x]), dc0 = __ldg(&g_dis[c4.x]), h0a = __ldg(&g_h0[r4.x]);
            float dr1 = __ldg(&g_dis[r4.y]), dc1 = __ldg(&g_dis[c4.y]), h0b = __ldg(&g_h0[r4.y]);
            float dr2 = __ldg(&g_dis[r4.z]), dc2 = __ldg(&g_dis[c4.z]), h0c = __ldg(&g_h0[r4.z]);
            float dr3 = __ldg(&g_dis[r4.w]), dc3 = __ldg(&g_dis[c4.w]), h0d = __ldg(&g_h0[r4.w]);
            float w0 = dr0 * dc0, w1 = dr1 * dc1, w2 = dr2 * dc2, w3 = dr3 * dc3;
            *reinterpret_cast<float4*>(&g_wedge[e]) = make_float4(w0, w1, w2, w3);
            atomicAdd(&g_h1[c4.x], w0 * h0a);
            atomicAdd(&g_h1[c4.y], w1 * h0b);
            atomicAdd(&g_h1[c4.z], w2 * h0c);
            atomicAdd(&g_h1[c4.w], w3 * h0d);
        }
    }
}

// K5: round 2 — self term + edge scatter using cached wedge (1 gather/edge)
__global__ void k_round2(const int* __restrict__ ei, float* __restrict__ out) {
    int t = blockIdx.x * blockDim.x + threadIdx.x;
    if (t < NODE_T) {
        float d = g_dis[t];
        atomicAdd(&out[t], d * d * g_h1[t]);
    } else {
        int e = (t - NODE_T) * 4;
        if (e < NEDGES) {
            int4 r4 = *reinterpret_cast<const int4*>(ei + e);
            int4 c4 = *reinterpret_cast<const int4*>(ei + NEDGES + e);
            float4 w4 = *reinterpret_cast<const float4*>(&g_wedge[e]);
            float h0a = __ldg(&g_h1[r4.x]);
            float h0b = __ldg(&g_h1[r4.y]);
            float h0c = __ldg(&g_h1[r4.z]);
            float h0d = __ldg(&g_h1[r4.w]);
            atomicAdd(&out[c4.x], w4.x * h0a);
            atomicAdd(&out[c4.y], w4.y * h0b);
            atomicAdd(&out[c4.z], w4.z * h0c);
            atomicAdd(&out[c4.w], w4.w * h0d);
        }
    }
}

extern "C" void kernel_launch(void* const* d_in, const int* in_sizes, int n_in,
                              void* d_out, int out_size) {
    const float* x  = (const float*)d_in[0];
    const int*   ei = (const int*)d_in[1];
    const float* W  = (const float*)d_in[2];
    const float* b  = (const float*)d_in[3];
    float* out = (float*)d_out;

    const int T = 256;
    const int gN   = (NNODES + T - 1) / T;
    const int gE4  = (NEDGES / 4 + T - 1) / T;
    const int gNE4 = (NNODES + NEDGES / 4 + T - 1) / T;
    const int gDot = ((NNODES / 4) * 32 + T - 1) / T;  // warp per 4 nodes

    k_init<<<gN, T>>>(out, b);
    k_count_deg<<<gE4, T>>>(ei);
    k_dot<<<gDot, T>>>(x, W);
    k_round1<<<gNE4, T>>>(ei);
    k_round2<<<gNE4, T>>>(ei, out);
}

// round 6
// speedup vs baseline: 1.0642x; 1.0642x over previous
#include <cuda_runtime.h>
#include <cuda_bf16.h>

#define NNODES 100000
#define NEDGES 600000
#define DFEAT  128

// Scratch
__device__ float g_dis[NNODES];    // deg -> rsqrt(deg)
__device__ float g_p[NNODES];      // p0 = dis * h0  (gather source, round 1)
__device__ float g_acc[NNODES];    // round-1 accumulator (init = p0)
__device__ float g_p2[NNODES];     // p1 = dis^2 * acc1 (gather source, round 2)
__device__ float g_acc2[NNODES];   // round-2 accumulator (init = p1)

// K1: deg = 1 (self loop)
__global__ void k_init() {
    int i = blockIdx.x * blockDim.x + threadIdx.x;
    if (i < NNODES) g_dis[i] = 1.0f;
}

// K2: degree count, 4 edges/thread
__global__ void k_count_deg(const int* __restrict__ ei) {
    int e = (blockIdx.x * blockDim.x + threadIdx.x) * 4;
    if (e < NEDGES) {
        int4 c4 = *reinterpret_cast<const int4*>(ei + NEDGES + e);
        atomicAdd(&g_dis[c4.x], 1.0f);
        atomicAdd(&g_dis[c4.y], 1.0f);
        atomicAdd(&g_dis[c4.z], 1.0f);
        atomicAdd(&g_dis[c4.w], 1.0f);
    }
}

// K3: dis = rsqrt(deg); s = x·w per node (4 nodes/warp);
//     p0 = dis*s, acc1 init = p0   (pre-pass of round 1 fused in)
__global__ void k_dot(const float* __restrict__ x, const float* __restrict__ w) {
    int warp_id = (blockIdx.x * blockDim.x + threadIdx.x) >> 5;
    int lane = threadIdx.x & 31;
    int base = warp_id * 4;
    if (base >= NNODES) return;   // NNODES % 4 == 0

    // lanes 0-3: normalize this quad's degrees, keep d in register
    float d = 0.0f;
    if (lane < 4) {
        d = rsqrtf(g_dis[base + lane]);
        g_dis[base + lane] = d;
    }

    const float4* wr = reinterpret_cast<const float4*>(w);
    float4 wv = __ldg(&wr[lane]);

    float4 xv0 = reinterpret_cast<const float4*>(x + (size_t)(base + 0) * DFEAT)[lane];
    float4 xv1 = reinterpret_cast<const float4*>(x + (size_t)(base + 1) * DFEAT)[lane];
    float4 xv2 = reinterpret_cast<const float4*>(x + (size_t)(base + 2) * DFEAT)[lane];
    float4 xv3 = reinterpret_cast<const float4*>(x + (size_t)(base + 3) * DFEAT)[lane];

    float s0 = xv0.x * wv.x + xv0.y * wv.y + xv0.z * wv.z + xv0.w * wv.w;
    float s1 = xv1.x * wv.x + xv1.y * wv.y + xv1.z * wv.z + xv1.w * wv.w;
    float s2 = xv2.x * wv.x + xv2.y * wv.y + xv2.z * wv.z + xv2.w * wv.w;
    float s3 = xv3.x * wv.x + xv3.y * wv.y + xv3.z * wv.z + xv3.w * wv.w;

    #pragma unroll
    for (int off = 16; off > 0; off >>= 1) {
        s0 += __shfl_xor_sync(0xFFFFFFFFu, s0, off);
        s1 += __shfl_xor_sync(0xFFFFFFFFu, s1, off);
        s2 += __shfl_xor_sync(0xFFFFFFFFu, s2, off);
        s3 += __shfl_xor_sync(0xFFFFFFFFu, s3, off);
    }

    // broadcast quad's dis values to lane 0
    float d0 = __shfl_sync(0xFFFFFFFFu, d, 0);
    float d1 = __shfl_sync(0xFFFFFFFFu, d, 1);
    float d2 = __shfl_sync(0xFFFFFFFFu, d, 2);
    float d3 = __shfl_sync(0xFFFFFFFFu, d, 3);

    if (lane == 0) {
        float4 p = make_float4(d0 * s0, d1 * s1, d2 * s2, d3 * s3);
        *reinterpret_cast<float4*>(&g_p[base])   = p;
        *reinterpret_cast<float4*>(&g_acc[base]) = p;   // self-loop term
    }
}

// K4: round-1 edges: acc1[col] += p0[row]  (1 gather + 1 atomic per edge)
__global__ void k_edge1(const int* __restrict__ ei) {
    int e = (blockIdx.x * blockDim.x + threadIdx.x) * 2;
    if (e < NEDGES) {
        int2 r2 = *reinterpret_cast<const int2*>(ei + e);
        int2 c2 = *reinterpret_cast<const int2*>(ei + NEDGES + e);
        float pa = __ldg(&g_p[r2.x]);
        float pb = __ldg(&g_p[r2.y]);
        atomicAdd(&g_acc[c2.x], pa);
        atomicAdd(&g_acc[c2.y], pb);
    }
}

// K5: between rounds: p1 = dis^2 * acc1 ; acc2 init = p1
__global__ void k_pre2() {
    int i = blockIdx.x * blockDim.x + threadIdx.x;
    if (i < NNODES) {
        float dd = g_dis[i];
        float v = dd * dd * g_acc[i];
        g_p2[i]   = v;
        g_acc2[i] = v;
    }
}

// K6: round-2 edges: acc2[col] += p1[row]
__global__ void k_edge2(const int* __restrict__ ei) {
    int e = (blockIdx.x * blockDim.x + threadIdx.x) * 2;
    if (e < NEDGES) {
        int2 r2 = *reinterpret_cast<const int2*>(ei + e);
        int2 c2 = *reinterpret_cast<const int2*>(ei + NEDGES + e);
        float pa = __ldg(&g_p2[r2.x]);
        float pb = __ldg(&g_p2[r2.y]);
        atomicAdd(&g_acc2[c2.x], pa);
        atomicAdd(&g_acc2[c2.y], pb);
    }
}

// K7: out = dis * acc2 + b
__global__ void k_post(float* __restrict__ out, const float* __restrict__ b) {
    int i = blockIdx.x * blockDim.x + threadIdx.x;
    if (i < NNODES) {
        out[i] = g_dis[i] * g_acc2[i] + b[0];
    }
}

extern "C" void kernel_launch(void* const* d_in, const int* in_sizes, int n_in,
                              void* d_out, int out_size) {
    const float* x  = (const float*)d_in[0];
    const int*   ei = (const int*)d_in[1];
    const float* W  = (const float*)d_in[2];
    const float* b  = (const float*)d_in[3];
    float* out = (float*)d_out;

    const int T = 256;
    const int gN   = (NNODES + T - 1) / T;
    const int gE4  = (NEDGES / 4 + T - 1) / T;
    const int gE2  = (NEDGES / 2 + T - 1) / T;
    const int gDot = ((NNODES / 4) * 32 + T - 1) / T;  // warp per 4 nodes

    k_init<<<gN, T>>>();
    k_count_deg<<<gE4, T>>>(ei);
    k_dot<<<gDot, T>>>(x, W);
    k_edge1<<<gE2, T>>>(ei);
    k_pre2<<<gN, T>>>();
    k_edge2<<<gE2, T>>>(ei);
    k_post<<<gN, T>>>(out, b);
}